// round 7
// baseline (speedup 1.0000x reference)
#include <cuda_runtime.h>
#include <cstdint>

// Problem constants
#define Bn 16384
#define Fn 512
#define Pn 128
#define Cn 10

// Tiling
#define BM 64                 // rows per block
#define BK 32                 // K tile
#define NT 256                // threads
#define NTILE (Fn / BK)       // 16
#define NSTG 3                // cp.async stages
#define STG_B 27648           // bytes per stage: A(64x144) + B(128x144)
#define B_OFF 9216            // B offset within a stage
#define OFF_TAIL (NSTG * STG_B)   // 82944
#define SROW 132              // si row stride (words)
#define UW 16                 // u_t row stride (words)
#define SMEM_BYTES (OFF_TAIL + (64 + 128 + 128 * UW + 128 + 128) * 4)

__device__ __forceinline__ uint32_t cvta_s(const void* p) {
    return (uint32_t)__cvta_generic_to_shared(p);
}
__device__ __forceinline__ void cp16(uint32_t dst, const void* src) {
    asm volatile("cp.async.ca.shared.global [%0], [%1], 16;" :: "r"(dst), "l"(src));
}
template <int N>
__device__ __forceinline__ void cp_wait() {
    asm volatile("cp.async.wait_group %0;" :: "n"(N) : "memory");
}
__device__ __forceinline__ void ldsm4(uint32_t* r, uint32_t addr) {
    asm volatile("ldmatrix.sync.aligned.m8n8.x4.shared.b16 {%0,%1,%2,%3}, [%4];"
        : "=r"(r[0]), "=r"(r[1]), "=r"(r[2]), "=r"(r[3]) : "r"(addr));
}
#define MMA_TF32(cc, a0, a1, a2, a3, b0, b1)                                     \
    asm volatile(                                                                \
        "mma.sync.aligned.m16n8k8.row.col.f32.tf32.tf32.f32 "                    \
        "{%0,%1,%2,%3},{%4,%5,%6,%7},{%8,%9},{%0,%1,%2,%3};"                     \
        : "+f"((cc)[0]), "+f"((cc)[1]), "+f"((cc)[2]), "+f"((cc)[3])             \
        : "r"(a0), "r"(a1), "r"(a2), "r"(a3), "r"(b0), "r"(b1))

__global__ __launch_bounds__(NT, 2)
void ds_kernel(const float* __restrict__ x, const float* __restrict__ w,
               const float* __restrict__ eta, const float* __restrict__ xi,
               const float* __restrict__ beta, float* __restrict__ out)
{
    extern __shared__ char smem[];
    float* sit = (float*)smem;                      // aliases stages post-GEMM
    float* xsq = (float*)(smem + OFF_TAIL);         // [64]
    float* wsq = xsq + 64;                          // [128]
    float* u_t = wsq + 128;                         // [128][UW]
    float* alp = u_t + 128 * UW;                    // [128]
    float* gam = alp + 128;                         // [128]

    const int tid  = threadIdx.x;
    const int row0 = blockIdx.x * BM;
    const uint32_t sbase = cvta_s(smem);

    // ---- async copy mapping: 6x16B per thread per tile (2 A rows, 4 B rows) ----
    const int r8 = tid >> 3;      // 0..31
    const int q8 = tid & 7;
    const float4* xg = (const float4*)x;   // 128 float4 per row
    const float4* wg = (const float4*)w;

#define COPY(t, stg)                                                              \
    do {                                                                          \
        uint32_t ad = sbase + (stg) * STG_B + r8 * 144 + q8 * 16;                 \
        uint32_t bd = ad + B_OFF;                                                 \
        const float4* xs_ = xg + (size_t)(row0 + r8) * 128 + (t) * 8 + q8;        \
        const float4* ws_ = wg + (size_t)r8 * 128 + (t) * 8 + q8;                 \
        cp16(ad, xs_);                                                            \
        cp16(ad + 32 * 144, xs_ + (size_t)32 * 128);                              \
        cp16(bd, ws_);                                                            \
        cp16(bd + 32 * 144, ws_ + (size_t)32 * 128);                              \
        cp16(bd + 64 * 144, ws_ + (size_t)64 * 128);                              \
        cp16(bd + 96 * 144, ws_ + (size_t)96 * 128);                              \
        asm volatile("cp.async.commit_group;" ::: "memory");                      \
    } while (0)

    COPY(0, 0);
    COPY(1, 1);

    // ---- prologue (hidden under first cp.async latency) ----
    // wsq[p] = ||w_p||^2 from global: 2 threads per row, 64 float4 each
    {
        const int wrow = tid >> 1;
        const float4* wr = wg + (size_t)wrow * 128 + (tid & 1) * 64;
        float acc0 = 0.f, acc1 = 0.f;
        #pragma unroll 8
        for (int j = 0; j < 64; j += 2) {
            float4 v = wr[j];
            acc0 += v.x * v.x + v.y * v.y + v.z * v.z + v.w * v.w;
            float4 u = wr[j + 1];
            acc1 += u.x * u.x + u.y * u.y + u.z * u.z + u.w * u.w;
        }
        float s = acc0 + acc1;
        s += __shfl_xor_sync(0xffffffffu, s, 1);
        if ((tid & 1) == 0) wsq[wrow] = s;
    }

    // per-prototype tables
    if (tid < Pn) {
        const int p = tid;
        float e = eta[p];
        gam[p] = e * e;
        alp[p] = 1.0f / (1.0f + __expf(-xi[p]));
        float b2[Cn];
        float bs = 0.0f;
        #pragma unroll
        for (int c = 0; c < Cn; c++) {
            float bv = beta[c * Pn + p];
            b2[c] = bv * bv;
            bs += b2[c];
        }
        float invb = 1.0f / bs;
        #pragma unroll
        for (int s = 0; s < UW; s++) u_t[p * UW + s] = 0.0f;
        #pragma unroll
        for (int c = 0; c < Cn; c++) {
            const int slot = (c < 9) ? (c / 3) * 4 + (c % 3) : 12;
            u_t[p * UW + slot] = b2[c] * invb;
        }
    }

    // ---- fragment addresses ----
    const int warp = tid >> 5, lane = tid & 31;
    const int m0 = (warp & 1) * 32;            // warp M base
    const int n0 = (warp >> 1) * 32;           // warp N base
    const int lr = lane >> 2, lc = lane & 3;

    const uint32_t aAddr0 = sbase + (m0 + (lane & 15)) * 144 + ((lane & 16) ? 16 : 0);
    const uint32_t aAddr1 = aAddr0 + 16 * 144;
    const uint32_t bAddr0 = sbase + B_OFF + (n0 + ((lane >> 4) & 1) * 8 + (lane & 7)) * 144
                                          + ((lane & 8) ? 16 : 0);
    const uint32_t bAddr1 = bAddr0 + 16 * 144;

    // x sumsq readback offset within a stage (8 floats of row tid>>2)
    const uint32_t xqOff = (tid >> 2) * 144 + (tid & 3) * 32;

    float acc[2][4][4];
    #pragma unroll
    for (int mi = 0; mi < 2; mi++)
        #pragma unroll
        for (int nj = 0; nj < 4; nj++)
            #pragma unroll
            for (int e = 0; e < 4; e++) acc[mi][nj][e] = 0.0f;

    float xacc = 0.0f;

    uint32_t fA[2][8], fB[2][8];

#define LDK(bf, so_, k8)                                                          \
    do {                                                                          \
        ldsm4(&fA[bf][0], aAddr0 + (so_) + (k8) * 32);                            \
        ldsm4(&fA[bf][4], aAddr1 + (so_) + (k8) * 32);                            \
        ldsm4(&fB[bf][0], bAddr0 + (so_) + (k8) * 32);                            \
        ldsm4(&fB[bf][4], bAddr1 + (so_) + (k8) * 32);                            \
    } while (0)

#define MMK(bf)                                                                   \
    do {                                                                          \
        MMA_TF32(acc[0][0], fA[bf][0], fA[bf][1], fA[bf][2], fA[bf][3],           \
                 fB[bf][0], fB[bf][1]);                                           \
        MMA_TF32(acc[0][1], fA[bf][0], fA[bf][1], fA[bf][2], fA[bf][3],           \
                 fB[bf][2], fB[bf][3]);                                           \
        MMA_TF32(acc[0][2], fA[bf][0], fA[bf][1], fA[bf][2], fA[bf][3],           \
                 fB[bf][4], fB[bf][5]);                                           \
        MMA_TF32(acc[0][3], fA[bf][0], fA[bf][1], fA[bf][2], fA[bf][3],           \
                 fB[bf][6], fB[bf][7]);                                           \
        MMA_TF32(acc[1][0], fA[bf][4], fA[bf][5], fA[bf][6], fA[bf][7],           \
                 fB[bf][0], fB[bf][1]);                                           \
        MMA_TF32(acc[1][1], fA[bf][4], fA[bf][5], fA[bf][6], fA[bf][7],           \
                 fB[bf][2], fB[bf][3]);                                           \
        MMA_TF32(acc[1][2], fA[bf][4], fA[bf][5], fA[bf][6], fA[bf][7],           \
                 fB[bf][4], fB[bf][5]);                                           \
        MMA_TF32(acc[1][3], fA[bf][4], fA[bf][5], fA[bf][6], fA[bf][7],           \
                 fB[bf][6], fB[bf][7]);                                           \
    } while (0)

    for (int t = 0; t < NTILE; t++) {
        const int stg = t % NSTG;
        if (t < NTILE - 1) cp_wait<1>();
        else               cp_wait<0>();
        __syncthreads();
        // stage (t+2)%3 was last consumed at tile t-1; all warps past it now
        if (t + 2 < NTILE) COPY(t + 2, (t + 2) % NSTG);

        // x sumsq partials from exact fp32 bits
        {
            const char* sb = smem + stg * STG_B;
            float4 v = *(const float4*)(sb + xqOff);
            xacc += v.x * v.x + v.y * v.y + v.z * v.z + v.w * v.w;
            v = *(const float4*)(sb + xqOff + 16);
            xacc += v.x * v.x + v.y * v.y + v.z * v.z + v.w * v.w;
        }

        const uint32_t so = stg * STG_B;
        LDK(0, so, 0);
        #pragma unroll
        for (int k8 = 0; k8 < 4; k8++) {
            if (k8 < 3) LDK((k8 + 1) & 1, so, k8 + 1);
            MMK(k8 & 1);
        }
    }

    // ---- reduce x sumsq ----
    {
        float v = xacc;
        v += __shfl_xor_sync(0xffffffffu, v, 1);
        v += __shfl_xor_sync(0xffffffffu, v, 2);
        if ((tid & 3) == 0) xsq[tid >> 2] = v;
    }
    __syncthreads();   // fences last MMA-stage reads before sit aliases stages

    // ---- epilogue: si = alpha * exp(-gamma * d) ----
    #pragma unroll
    for (int mi = 0; mi < 2; mi++) {
        const int r0_ = m0 + mi * 16 + lr;
        const int r1_ = r0_ + 8;
        const float xq0 = xsq[r0_];
        const float xq1 = xsq[r1_];
        #pragma unroll
        for (int nj = 0; nj < 4; nj++) {
            const int c0 = n0 + nj * 8 + 2 * lc;
            const int c1 = c0 + 1;
            const float wq0 = wsq[c0], wq1 = wsq[c1];
            float d00 = xq0 + wq0 - 2.0f * acc[mi][nj][0];
            float d01 = xq0 + wq1 - 2.0f * acc[mi][nj][1];
            float d10 = xq1 + wq0 - 2.0f * acc[mi][nj][2];
            float d11 = xq1 + wq1 - 2.0f * acc[mi][nj][3];
            sit[r0_ * SROW + c0] = alp[c0] * __expf(-gam[c0] * d00);
            sit[r0_ * SROW + c1] = alp[c1] * __expf(-gam[c1] * d01);
            sit[r1_ * SROW + c0] = alp[c0] * __expf(-gam[c0] * d10);
            sit[r1_ * SROW + c1] = alp[c1] * __expf(-gam[c1] * d11);
        }
    }
    __syncthreads();

    // ---- scan: 4 threads per row, linear s-space recurrence (R5-proven) ----
    {
        const int row = tid >> 2;
        const int g   = tid & 3;
        const float* srow = sit + row * SROW;

        float mx = -1e30f;
        #pragma unroll
        for (int j = 0; j < 8; j++) {
            float4 v = *(const float4*)&srow[g * 32 + j * 4];
            mx = fmaxf(mx, fmaxf(fmaxf(v.x, v.y), fmaxf(v.z, v.w)));
        }
        mx = fmaxf(mx, __shfl_xor_sync(0xffffffffu, mx, 1));
        mx = fmaxf(mx, __shfl_xor_sync(0xffffffffu, mx, 2));
        const float inv = 1.0f / (mx + 1e-4f);

        float s0_, s1_, s2_, o;
        {
            const float sp = srow[0] * inv;
            const float4 u4 = *(const float4*)&u_t[0 * UW + g * 4];
            o = 1.0f - sp;
            s0_ = fmaf(u4.x, sp, o);
            s1_ = fmaf(u4.y, sp, o);
            s2_ = fmaf(u4.z, sp, o);
        }

        #pragma unroll 8
        for (int p = 1; p < Pn; p++) {
            const float sp = srow[p] * inv;
            const float4 u4 = *(const float4*)&u_t[p * UW + g * 4];
            const float o2 = 1.0f - sp;
            const float oo2 = o * o2;
            const float add = oo2 + oo2;
            s0_ = fmaf(s0_, fmaf(u4.x, sp, o2), add);
            s1_ = fmaf(s1_, fmaf(u4.y, sp, o2), add);
            s2_ = fmaf(s2_, fmaf(u4.z, sp, o2), add);
            o = 3.0f * oo2;
            if ((p & 7) == 7) {   // periodic renormalization (pure rescale)
                float part = (g == 3) ? s0_ : (s0_ + s1_ + s2_);
                part += __shfl_xor_sync(0xffffffffu, part, 1);
                part += __shfl_xor_sync(0xffffffffu, part, 2);
                const float rr = __fdividef(1.0f, part - 9.0f * o);
                s0_ *= rr; s1_ *= rr; s2_ *= rr; o *= rr;
            }
        }

        float part = (g == 3) ? s0_ : (s0_ + s1_ + s2_);
        part += __shfl_xor_sync(0xffffffffu, part, 1);
        part += __shfl_xor_sync(0xffffffffu, part, 2);
        const float rr = __fdividef(1.0f, part - 9.0f * o);

        float* orow = out + (size_t)(row0 + row) * (Cn + 1);
        if (g < 3) {
            orow[3 * g + 0] = (s0_ - o) * rr;
            orow[3 * g + 1] = (s1_ - o) * rr;
            orow[3 * g + 2] = (s2_ - o) * rr;
        } else {
            orow[9]  = (s0_ - o) * rr;
            orow[10] = o * rr;
        }
    }
}

extern "C" void kernel_launch(void* const* d_in, const int* in_sizes, int n_in,
                              void* d_out, int out_size)
{
    const float* x    = (const float*)d_in[0];
    const float* w    = (const float*)d_in[1];
    const float* eta  = (const float*)d_in[2];
    const float* xi   = (const float*)d_in[3];
    const float* beta = (const float*)d_in[4];
    float* out = (float*)d_out;

    cudaFuncSetAttribute(ds_kernel, cudaFuncAttributeMaxDynamicSharedMemorySize,
                         SMEM_BYTES);

    ds_kernel<<<Bn / BM, NT, SMEM_BYTES>>>(x, w, eta, xi, beta, out);
}

// round 8
// speedup vs baseline: 1.3171x; 1.3171x over previous
#include <cuda_runtime.h>
#include <cstdint>

// Problem constants
#define Bn 16384
#define Fn 512
#define Pn 128
#define Cn 10

// Tiling
#define BM 64                 // rows per block
#define BK 32                 // K tile
#define NT 512                // threads (16 warps: 4M x 4N)
#define NTILE (Fn / BK)       // 16
#define NSTG 3                // cp.async stages
#define STG_B 27648           // bytes per stage: A(64x144) + B(128x144)
#define B_OFF 9216            // B offset within a stage
#define OFF_TAIL (NSTG * STG_B)   // 82944
#define SROW 132              // si row stride (words)
#define UW 16                 // u_t row stride (words)
#define SMEM_BYTES (OFF_TAIL + (64 + 128 + 128 * UW + 128 + 128) * 4)

__device__ __forceinline__ uint32_t cvta_s(const void* p) {
    return (uint32_t)__cvta_generic_to_shared(p);
}
__device__ __forceinline__ void cp16(uint32_t dst, const void* src) {
    asm volatile("cp.async.ca.shared.global [%0], [%1], 16;" :: "r"(dst), "l"(src));
}
template <int N>
__device__ __forceinline__ void cp_wait() {
    asm volatile("cp.async.wait_group %0;" :: "n"(N) : "memory");
}
__device__ __forceinline__ void ldsm4(uint32_t* r, uint32_t addr) {
    asm volatile("ldmatrix.sync.aligned.m8n8.x4.shared.b16 {%0,%1,%2,%3}, [%4];"
        : "=r"(r[0]), "=r"(r[1]), "=r"(r[2]), "=r"(r[3]) : "r"(addr));
}
#define MMA_TF32(cc, a0, a1, a2, a3, b0, b1)                                     \
    asm volatile(                                                                \
        "mma.sync.aligned.m16n8k8.row.col.f32.tf32.tf32.f32 "                    \
        "{%0,%1,%2,%3},{%4,%5,%6,%7},{%8,%9},{%0,%1,%2,%3};"                     \
        : "+f"((cc)[0]), "+f"((cc)[1]), "+f"((cc)[2]), "+f"((cc)[3])             \
        : "r"(a0), "r"(a1), "r"(a2), "r"(a3), "r"(b0), "r"(b1))

__global__ __launch_bounds__(NT, 2)
void ds_kernel(const float* __restrict__ x, const float* __restrict__ w,
               const float* __restrict__ eta, const float* __restrict__ xi,
               const float* __restrict__ beta, float* __restrict__ out)
{
    extern __shared__ char smem[];
    float* sit = (float*)smem;                      // aliases stages post-GEMM
    float* xsq = (float*)(smem + OFF_TAIL);         // [64]
    float* wsq = xsq + 64;                          // [128]
    float* u_t = wsq + 128;                         // [128][UW]
    float* alp = u_t + 128 * UW;                    // [128]
    float* gam = alp + 128;                         // [128]

    const int tid  = threadIdx.x;
    const int row0 = blockIdx.x * BM;
    const uint32_t sbase = cvta_s(smem);

    // ---- async copy mapping: 3x16B per thread per tile (1 A row, 2 B rows) ----
    const int oct = tid >> 3;     // 0..63 (row index)
    const int q8  = tid & 7;      // float4 slot within 32-float row
    const float4* xg = (const float4*)x;   // 128 float4 per row
    const float4* wg = (const float4*)w;

#define COPY(t, stg)                                                              \
    do {                                                                          \
        uint32_t ad = sbase + (stg) * STG_B + oct * 144 + q8 * 16;                \
        uint32_t bd = ad + B_OFF;                                                 \
        cp16(ad, xg + (size_t)(row0 + oct) * 128 + (t) * 8 + q8);                 \
        cp16(bd, wg + (size_t)oct * 128 + (t) * 8 + q8);                          \
        cp16(bd + 64 * 144, wg + (size_t)(oct + 64) * 128 + (t) * 8 + q8);        \
        asm volatile("cp.async.commit_group;" ::: "memory");                      \
    } while (0)

    COPY(0, 0);
    COPY(1, 1);

    // ---- per-prototype tables (overlapped with first copies) ----
    if (tid < Pn) {
        const int p = tid;
        float e = eta[p];
        gam[p] = e * e;
        alp[p] = 1.0f / (1.0f + __expf(-xi[p]));
        float b2[Cn];
        float bs = 0.0f;
        #pragma unroll
        for (int c = 0; c < Cn; c++) {
            float bv = beta[c * Pn + p];
            b2[c] = bv * bv;
            bs += b2[c];
        }
        float invb = 1.0f / bs;
        #pragma unroll
        for (int s = 0; s < UW; s++) u_t[p * UW + s] = 0.0f;
        #pragma unroll
        for (int c = 0; c < Cn; c++) {
            const int slot = (c < 9) ? (c / 3) * 4 + (c % 3) : 12;
            u_t[p * UW + slot] = b2[c] * invb;
        }
    }

    // ---- fragment addresses: warp (4M x 4N), warp tile 16x32 ----
    const int warp = tid >> 5, lane = tid & 31;
    const int m0 = (warp & 3) * 16;            // warp M base
    const int n0 = (warp >> 2) * 32;           // warp N base
    const int lr = lane >> 2, lc = lane & 3;

    const uint32_t aAddr  = sbase + (m0 + (lane & 15)) * 144 + ((lane & 16) ? 16 : 0);
    const uint32_t bAddr0 = sbase + B_OFF + (n0 + ((lane >> 4) & 1) * 8 + (lane & 7)) * 144
                                          + ((lane & 8) ? 16 : 0);
    const uint32_t bAddr1 = bAddr0 + 16 * 144;

    // sumsq readback offsets (own stashed bytes; exact fp32 bits)
    const uint32_t sqOff = oct * 144 + q8 * 16;

    float acc[4][4];
    #pragma unroll
    for (int nj = 0; nj < 4; nj++)
        #pragma unroll
        for (int e = 0; e < 4; e++) acc[nj][e] = 0.0f;

    float xacc = 0.0f, wacc0 = 0.0f, wacc1 = 0.0f;

    for (int t = 0; t < NTILE; t++) {
        const int stg = t % NSTG;
        if (t < NTILE - 1) cp_wait<1>();
        else               cp_wait<0>();
        __syncthreads();
        // stage (t+2)%3 last consumed at tile t-1; all warps past it now
        if (t + 2 < NTILE) COPY(t + 2, (t + 2) % NSTG);

        // sumsq partials
        {
            const char* sb = smem + stg * STG_B;
            float4 v = *(const float4*)(sb + sqOff);
            xacc += v.x * v.x + v.y * v.y + v.z * v.z + v.w * v.w;
            v = *(const float4*)(sb + B_OFF + sqOff);
            wacc0 += v.x * v.x + v.y * v.y + v.z * v.z + v.w * v.w;
            v = *(const float4*)(sb + B_OFF + 64 * 144 + sqOff);
            wacc1 += v.x * v.x + v.y * v.y + v.z * v.z + v.w * v.w;
        }

        const uint32_t so = stg * STG_B;
        #pragma unroll
        for (int k8 = 0; k8 < 4; k8++) {
            uint32_t a[4], b0[4], b1[4];
            ldsm4(a,  aAddr  + so + k8 * 32);
            ldsm4(b0, bAddr0 + so + k8 * 32);
            ldsm4(b1, bAddr1 + so + k8 * 32);
            MMA_TF32(acc[0], a[0], a[1], a[2], a[3], b0[0], b0[1]);
            MMA_TF32(acc[1], a[0], a[1], a[2], a[3], b0[2], b0[3]);
            MMA_TF32(acc[2], a[0], a[1], a[2], a[3], b1[0], b1[1]);
            MMA_TF32(acc[3], a[0], a[1], a[2], a[3], b1[2], b1[3]);
        }
    }

    // ---- reduce sumsq (8 threads per row -> shfl over octet) ----
    {
        float v = xacc;
        v += __shfl_xor_sync(0xffffffffu, v, 1);
        v += __shfl_xor_sync(0xffffffffu, v, 2);
        v += __shfl_xor_sync(0xffffffffu, v, 4);
        if (q8 == 0) xsq[oct] = v;
        float u = wacc0;
        u += __shfl_xor_sync(0xffffffffu, u, 1);
        u += __shfl_xor_sync(0xffffffffu, u, 2);
        u += __shfl_xor_sync(0xffffffffu, u, 4);
        if (q8 == 0) wsq[oct] = u;
        float u1 = wacc1;
        u1 += __shfl_xor_sync(0xffffffffu, u1, 1);
        u1 += __shfl_xor_sync(0xffffffffu, u1, 2);
        u1 += __shfl_xor_sync(0xffffffffu, u1, 4);
        if (q8 == 0) wsq[oct + 64] = u1;
    }
    __syncthreads();   // fences last MMA-stage reads before sit aliases stages

    // ---- epilogue: si = alpha * exp(-gamma * d) ----
    {
        const int r0_ = m0 + lr;
        const int r1_ = r0_ + 8;
        const float xq0 = xsq[r0_];
        const float xq1 = xsq[r1_];
        #pragma unroll
        for (int nj = 0; nj < 4; nj++) {
            const int c0 = n0 + nj * 8 + 2 * lc;
            const int c1 = c0 + 1;
            const float wq0 = wsq[c0], wq1 = wsq[c1];
            float d00 = xq0 + wq0 - 2.0f * acc[nj][0];
            float d01 = xq0 + wq1 - 2.0f * acc[nj][1];
            float d10 = xq1 + wq0 - 2.0f * acc[nj][2];
            float d11 = xq1 + wq1 - 2.0f * acc[nj][3];
            sit[r0_ * SROW + c0] = alp[c0] * __expf(-gam[c0] * d00);
            sit[r0_ * SROW + c1] = alp[c1] * __expf(-gam[c1] * d01);
            sit[r1_ * SROW + c0] = alp[c0] * __expf(-gam[c0] * d10);
            sit[r1_ * SROW + c1] = alp[c1] * __expf(-gam[c1] * d11);
        }
    }
    __syncthreads();

    // ---- scan: 4 threads per row (first 256 threads), linear recurrence ----
    if (tid < 4 * BM) {
        const int row = tid >> 2;
        const int g   = tid & 3;
        const float* srow = sit + row * SROW;

        float mx = -1e30f;
        #pragma unroll
        for (int j = 0; j < 8; j++) {
            float4 v = *(const float4*)&srow[g * 32 + j * 4];
            mx = fmaxf(mx, fmaxf(fmaxf(v.x, v.y), fmaxf(v.z, v.w)));
        }
        mx = fmaxf(mx, __shfl_xor_sync(0xffffffffu, mx, 1));
        mx = fmaxf(mx, __shfl_xor_sync(0xffffffffu, mx, 2));
        const float inv = 1.0f / (mx + 1e-4f);

        float s0_, s1_, s2_, o;
        {
            const float sp = srow[0] * inv;
            const float4 u4 = *(const float4*)&u_t[0 * UW + g * 4];
            o = 1.0f - sp;
            s0_ = fmaf(u4.x, sp, o);
            s1_ = fmaf(u4.y, sp, o);
            s2_ = fmaf(u4.z, sp, o);
        }

        #pragma unroll 8
        for (int p = 1; p < Pn; p++) {
            const float sp = srow[p] * inv;
            const float4 u4 = *(const float4*)&u_t[p * UW + g * 4];
            const float o2 = 1.0f - sp;
            const float oo2 = o * o2;
            const float add = oo2 + oo2;
            s0_ = fmaf(s0_, fmaf(u4.x, sp, o2), add);
            s1_ = fmaf(s1_, fmaf(u4.y, sp, o2), add);
            s2_ = fmaf(s2_, fmaf(u4.z, sp, o2), add);
            o = 3.0f * oo2;
            if ((p & 7) == 7) {   // periodic renormalization (pure rescale)
                float part = (g == 3) ? s0_ : (s0_ + s1_ + s2_);
                part += __shfl_xor_sync(0xffffffffu, part, 1);
                part += __shfl_xor_sync(0xffffffffu, part, 2);
                const float rr = __fdividef(1.0f, part - 9.0f * o);
                s0_ *= rr; s1_ *= rr; s2_ *= rr; o *= rr;
            }
        }

        float part = (g == 3) ? s0_ : (s0_ + s1_ + s2_);
        part += __shfl_xor_sync(0xffffffffu, part, 1);
        part += __shfl_xor_sync(0xffffffffu, part, 2);
        const float rr = __fdividef(1.0f, part - 9.0f * o);

        float* orow = out + (size_t)(row0 + row) * (Cn + 1);
        if (g < 3) {
            orow[3 * g + 0] = (s0_ - o) * rr;
            orow[3 * g + 1] = (s1_ - o) * rr;
            orow[3 * g + 2] = (s2_ - o) * rr;
        } else {
            orow[9]  = (s0_ - o) * rr;
            orow[10] = o * rr;
        }
    }
}

extern "C" void kernel_launch(void* const* d_in, const int* in_sizes, int n_in,
                              void* d_out, int out_size)
{
    const float* x    = (const float*)d_in[0];
    const float* w    = (const float*)d_in[1];
    const float* eta  = (const float*)d_in[2];
    const float* xi   = (const float*)d_in[3];
    const float* beta = (const float*)d_in[4];
    float* out = (float*)d_out;

    cudaFuncSetAttribute(ds_kernel, cudaFuncAttributeMaxDynamicSharedMemorySize,
                         SMEM_BYTES);

    ds_kernel<<<Bn / BM, NT, SMEM_BYTES>>>(x, w, eta, xi, beta, out);
}